// round 1
// baseline (speedup 1.0000x reference)
#include <cuda_runtime.h>
#include <math.h>

// ---------------- model dims ----------------
#define NB_B 32
#define NB_S 512
#define NB_T (NB_B*NB_S)      // 16384 tokens
#define NB_D 384
#define NB_H 12
#define NB_HD 32
#define NB_FF 1536
#define NB_L 6

// ---------------- device scratch (allocation-free) ----------------
__device__ float g_x[NB_T*NB_D];      // activations
__device__ float g_q[NB_T*NB_D];
__device__ float g_k[NB_T*NB_D];
__device__ float g_v[NB_T*NB_D];
__device__ float g_o[NB_T*NB_D];      // deltanet output
__device__ float g_y[NB_T*NB_D];      // gemm output (Wo / W2)
__device__ float g_h[NB_T*NB_FF];     // ffn hidden
__device__ float g_beta[NB_T*NB_H];

// ---------------- helpers ----------------
__device__ __forceinline__ float wsum(float v) {
#pragma unroll
    for (int o = 16; o > 0; o >>= 1) v += __shfl_xor_sync(0xffffffffu, v, o);
    return v;
}

__device__ __forceinline__ float sigm(float x) { return 1.f / (1.f + expf(-x)); }

__device__ __forceinline__ float gelu_tanh(float x) {
    float x3 = x * x * x;
    return 0.5f * x * (1.f + tanhf(0.7978845608028654f * (x + 0.044715f * x3)));
}

// block reduce of two values; valid for blockDim.x <= 1024, multiple of 32
__device__ __forceinline__ void blockReduce2(float& a, float& b) {
    __shared__ float sa[32], sb[32];
    __syncthreads();                // protect reuse across calls
    a = wsum(a); b = wsum(b);
    int w = threadIdx.x >> 5, l = threadIdx.x & 31;
    int nw = (blockDim.x + 31) >> 5;
    if (l == 0) { sa[w] = a; sb[w] = b; }
    __syncthreads();
    if (w == 0) {
        float x = (l < nw) ? sa[l] : 0.f;
        float y = (l < nw) ? sb[l] : 0.f;
        x = wsum(x); y = wsum(y);
        if (l == 0) { sa[0] = x; sb[0] = y; }
    }
    __syncthreads();
    a = sa[0]; b = sb[0];
}

// ---------------- embedding + LN ----------------
__global__ void embed_ln_kernel(const int* __restrict__ ids,
                                const float* __restrict__ we,
                                const float* __restrict__ pe,
                                const float* __restrict__ te,
                                const float* __restrict__ gam,
                                const float* __restrict__ bet) {
    int t = blockIdx.x;
    int sp = t % NB_S;
    int id = ids[t];
    __shared__ float buf[NB_D];
    float s1 = 0.f, s2 = 0.f;
    for (int d = threadIdx.x; d < NB_D; d += blockDim.x) {
        float v = we[(size_t)id * NB_D + d] + pe[sp * NB_D + d] + te[d];
        buf[d] = v; s1 += v; s2 += v * v;
    }
    blockReduce2(s1, s2);
    float mean = s1 * (1.f / NB_D);
    float inv = rsqrtf(s2 * (1.f / NB_D) - mean * mean + 1e-12f);
    for (int d = threadIdx.x; d < NB_D; d += blockDim.x)
        g_x[t * NB_D + d] = (buf[d] - mean) * inv * gam[d] + bet[d];
}

// ---------------- residual add + LN (x = LN(x + y)) ----------------
__global__ void add_ln_kernel(const float* __restrict__ gam,
                              const float* __restrict__ bet) {
    int t = blockIdx.x;
    __shared__ float buf[NB_D];
    float s1 = 0.f, s2 = 0.f;
    for (int d = threadIdx.x; d < NB_D; d += blockDim.x) {
        float v = g_x[t * NB_D + d] + g_y[t * NB_D + d];
        buf[d] = v; s1 += v; s2 += v * v;
    }
    blockReduce2(s1, s2);
    float mean = s1 * (1.f / NB_D);
    float inv = rsqrtf(s2 * (1.f / NB_D) - mean * mean + 1e-12f);
    for (int d = threadIdx.x; d < NB_D; d += blockDim.x)
        g_x[t * NB_D + d] = (buf[d] - mean) * inv * gam[d] + bet[d];
}

// ---------------- SGEMM: C = act(A[MxK] @ B[KxN] + bias) ----------------
// BM=BN=64, BK=16, 256 threads, 4x4 per thread. M%64==0, N%64==0, K%16==0.
template <int ACT>
__global__ void sgemm_kernel(const float* __restrict__ A,
                             const float* __restrict__ Bm,
                             const float* __restrict__ bias,
                             float* __restrict__ C,
                             int M, int N, int K) {
    __shared__ float As[16][64];
    __shared__ float Bs[16][64];
    int tid = threadIdx.x;
    int m0 = blockIdx.y * 64, n0 = blockIdx.x * 64;
    int a_r = tid >> 2, a_k = (tid & 3) << 2;     // 64 rows x 16 k
    int b_k = tid >> 4, b_c = (tid & 15) << 2;    // 16 k x 64 cols
    int ty = tid >> 4, tx = tid & 15;

    float acc[4][4];
#pragma unroll
    for (int i = 0; i < 4; i++)
#pragma unroll
        for (int j = 0; j < 4; j++) acc[i][j] = 0.f;

    const float* Aptr = A + (size_t)(m0 + a_r) * K + a_k;
    const float* Bptr = Bm + (size_t)b_k * N + n0 + b_c;

    for (int k0 = 0; k0 < K; k0 += 16) {
        float4 av = *(const float4*)(Aptr + k0);
        float4 bv = *(const float4*)(Bptr + (size_t)k0 * N);
        As[a_k + 0][a_r] = av.x; As[a_k + 1][a_r] = av.y;
        As[a_k + 2][a_r] = av.z; As[a_k + 3][a_r] = av.w;
        *(float4*)(&Bs[b_k][b_c]) = bv;
        __syncthreads();
#pragma unroll
        for (int kk = 0; kk < 16; kk++) {
            float4 a4 = *(const float4*)(&As[kk][ty << 2]);
            float4 b4 = *(const float4*)(&Bs[kk][tx << 2]);
            float ar[4] = {a4.x, a4.y, a4.z, a4.w};
            float br[4] = {b4.x, b4.y, b4.z, b4.w};
#pragma unroll
            for (int i = 0; i < 4; i++)
#pragma unroll
                for (int j = 0; j < 4; j++) acc[i][j] += ar[i] * br[j];
        }
        __syncthreads();
    }

#pragma unroll
    for (int i = 0; i < 4; i++) {
        int r = m0 + (ty << 2) + i;
#pragma unroll
        for (int j = 0; j < 4; j++) {
            int c = n0 + (tx << 2) + j;
            float v = acc[i][j] + bias[c];
            if (ACT == 1) v = gelu_tanh(v);
            C[(size_t)r * N + c] = v;
        }
    }
}

// ---------------- beta = sigmoid(x @ Wb) * mask ----------------
// grid = T, block = 384 (12 warps, one per head)
__global__ void beta_kernel(const float* __restrict__ Wb,
                            const int* __restrict__ amask) {
    int t = blockIdx.x;
    int w = threadIdx.x >> 5, l = threadIdx.x & 31;
    const float* xr = g_x + (size_t)t * NB_D;
    float s = 0.f;
    for (int d = l; d < NB_D; d += 32) s += xr[d] * Wb[d * NB_H + w];
    s = wsum(s);
    if (l == 0)
        g_beta[t * NB_H + w] = (float)amask[t] * (1.f / (1.f + expf(-s)));
}

// ---------------- per-(token,head) L2 normalize q and k ----------------
// one warp per (t,h); grid*8 warps total = T*H
__global__ void qknorm_kernel() {
    int gw = blockIdx.x * 8 + (threadIdx.x >> 5);
    int l = threadIdx.x & 31;
    int t = gw / NB_H, h = gw % NB_H;
    int idx = t * NB_D + h * NB_HD + l;
    float qv = g_q[idx];
    float s = wsum(qv * qv);
    g_q[idx] = qv / (sqrtf(s) + 1e-6f);
    float kv = g_k[idx];
    s = wsum(kv * kv);
    g_k[idx] = kv / (sqrtf(s) + 1e-6f);
}

// ---------------- hierarchical delta-rule scan ----------------
// warp = one (b,h,vcol); lane = k-index. State element per thread: Sf, Ss.
// No cross-warp communication -> no __syncthreads in the loop.
__global__ void scan_kernel(const float* __restrict__ dfast,
                            const float* __restrict__ dslow,
                            const float* __restrict__ mixl) {
    int gw = blockIdx.x * (blockDim.x >> 5) + (threadIdx.x >> 5);
    int l = threadIdx.x & 31;
    int vcol = gw & 31;
    int bh = gw >> 5;             // 0 .. B*H-1
    int h = bh % NB_H;
    int b = bh / NB_H;

    float af = sigm(dfast[h]);
    float as_ = sigm(dslow[h]);
    float g = sigm(mixl[h]);
    float gi = 1.f - g;

    int rb = b * NB_S * NB_D + h * NB_HD;
    int bb = b * NB_S * NB_H + h;
    float Sf = 0.f, Ss = 0.f;

    for (int t = 0; t < NB_S; t++, rb += NB_D, bb += NB_H) {
        float kt = g_k[rb + l];
        float qt = g_q[rb + l];
        float vt = g_v[rb + vcol];   // broadcast load
        float bt = g_beta[bb];       // broadcast load
        float pf = wsum(Sf * kt);
        float ps = wsum(Ss * kt);
        float bk = bt * kt;
        Sf = af * Sf + bk * (vt - pf);
        Ss = as_ * Ss + bk * (vt - ps);
        float oc = wsum(qt * (g * Sf + gi * Ss));
        if (l == 0) g_o[rb + vcol] = oc;
    }
}

// ---------------- masked mean pool + L2 normalize ----------------
// grid = B, block = D
__global__ void pool_kernel(const int* __restrict__ amask,
                            float* __restrict__ out) {
    int b = blockIdx.x, d = threadIdx.x;
    float sum = 0.f, ms = 0.f;
    for (int s = 0; s < NB_S; s++) {
        float m = (float)amask[b * NB_S + s];
        sum += g_x[(size_t)(b * NB_S + s) * NB_D + d] * m;
        ms += m;
    }
    float pooled = sum / fmaxf(ms, 1e-9f);
    float sq = pooled * pooled;
    float dummy = 0.f;
    blockReduce2(sq, dummy);
    out[b * NB_D + d] = pooled * rsqrtf(sq);
}

// ---------------- launch ----------------
extern "C" void kernel_launch(void* const* d_in, const int* in_sizes, int n_in,
                              void* d_out, int out_size) {
    const int*   ids   = (const int*)d_in[0];
    const int*   amask = (const int*)d_in[1];
    const float* we    = (const float*)d_in[2];
    const float* pe    = (const float*)d_in[3];
    const float* te    = (const float*)d_in[4];
    const float* elg   = (const float*)d_in[5];
    const float* elb   = (const float*)d_in[6];
    const float* Wq    = (const float*)d_in[7];
    const float* bq    = (const float*)d_in[8];
    const float* Wk    = (const float*)d_in[9];
    const float* bk    = (const float*)d_in[10];
    const float* Wv    = (const float*)d_in[11];
    const float* bv    = (const float*)d_in[12];
    const float* Wb    = (const float*)d_in[13];
    const float* dfast = (const float*)d_in[14];
    const float* dslow = (const float*)d_in[15];
    const float* mixl  = (const float*)d_in[16];
    const float* Wo    = (const float*)d_in[17];
    const float* bo    = (const float*)d_in[18];
    const float* alg   = (const float*)d_in[19];
    const float* alb   = (const float*)d_in[20];
    const float* W1    = (const float*)d_in[21];
    const float* b1    = (const float*)d_in[22];
    const float* W2    = (const float*)d_in[23];
    const float* b2    = (const float*)d_in[24];
    const float* flg   = (const float*)d_in[25];
    const float* flb   = (const float*)d_in[26];
    float* out = (float*)d_out;

    float *p_x, *p_q, *p_k, *p_v, *p_o, *p_y, *p_h;
    cudaGetSymbolAddress((void**)&p_x, g_x);
    cudaGetSymbolAddress((void**)&p_q, g_q);
    cudaGetSymbolAddress((void**)&p_k, g_k);
    cudaGetSymbolAddress((void**)&p_v, g_v);
    cudaGetSymbolAddress((void**)&p_o, g_o);
    cudaGetSymbolAddress((void**)&p_y, g_y);
    cudaGetSymbolAddress((void**)&p_h, g_h);

    embed_ln_kernel<<<NB_T, 128>>>(ids, we, pe, te, elg, elb);

    dim3 gD(NB_D / 64, NB_T / 64);    // N=384
    dim3 gF(NB_FF / 64, NB_T / 64);   // N=1536

    for (int l = 0; l < NB_L; l++) {
        const float* wq = Wq + (size_t)l * NB_D * NB_D;
        const float* wk = Wk + (size_t)l * NB_D * NB_D;
        const float* wv = Wv + (size_t)l * NB_D * NB_D;
        const float* wo = Wo + (size_t)l * NB_D * NB_D;
        const float* w1 = W1 + (size_t)l * NB_D * NB_FF;
        const float* w2 = W2 + (size_t)l * NB_FF * NB_D;

        sgemm_kernel<0><<<gD, 256>>>(p_x, wq, bq + l * NB_D, p_q, NB_T, NB_D, NB_D);
        sgemm_kernel<0><<<gD, 256>>>(p_x, wk, bk + l * NB_D, p_k, NB_T, NB_D, NB_D);
        sgemm_kernel<0><<<gD, 256>>>(p_x, wv, bv + l * NB_D, p_v, NB_T, NB_D, NB_D);

        beta_kernel<<<NB_T, NB_H * 32>>>(Wb + (size_t)l * NB_D * NB_H, amask);
        qknorm_kernel<<<(NB_T * NB_H) / 8, 256>>>();
        scan_kernel<<<(NB_B * NB_H * NB_HD) / 4, 128>>>(
            dfast + l * NB_H, dslow + l * NB_H, mixl + l * NB_H);

        sgemm_kernel<0><<<gD, 256>>>(p_o, wo, bo + l * NB_D, p_y, NB_T, NB_D, NB_D);
        add_ln_kernel<<<NB_T, 128>>>(alg + l * NB_D, alb + l * NB_D);

        sgemm_kernel<1><<<gF, 256>>>(p_x, w1, b1 + l * NB_FF, p_h, NB_T, NB_FF, NB_D);
        sgemm_kernel<0><<<gD, 256>>>(p_h, w2, b2 + l * NB_D, p_y, NB_T, NB_D, NB_FF);
        add_ln_kernel<<<NB_T, 128>>>(flg + l * NB_D, flb + l * NB_D);
    }

    pool_kernel<<<NB_B, NB_D>>>(amask, out);
}

// round 2
// speedup vs baseline: 1.7217x; 1.7217x over previous
#include <cuda_runtime.h>
#include <math.h>
#include <stdint.h>

// ---------------- model dims ----------------
#define NB_B 32
#define NB_S 512
#define NB_T (NB_B*NB_S)      // 16384 tokens
#define NB_D 384
#define NB_H 12
#define NB_HD 32
#define NB_FF 1536
#define NB_L 6

// ---------------- device scratch (allocation-free) ----------------
__device__ float g_x[NB_T*NB_D];      // activations
__device__ float g_q[NB_T*NB_D];
__device__ float g_k[NB_T*NB_D];
__device__ float g_v[NB_T*NB_D];
__device__ float g_o[NB_T*NB_D];      // deltanet output
__device__ float g_y[NB_T*NB_D];      // gemm output (Wo / W2)
__device__ float g_h[NB_T*NB_FF];     // ffn hidden
__device__ float g_beta[NB_T*NB_H];

// ---------------- helpers ----------------
__device__ __forceinline__ float wsum(float v) {
#pragma unroll
    for (int o = 16; o > 0; o >>= 1) v += __shfl_xor_sync(0xffffffffu, v, o);
    return v;
}

__device__ __forceinline__ float sigm(float x) { return 1.f / (1.f + expf(-x)); }

__device__ __forceinline__ float gelu_tanh(float x) {
    float x3 = x * x * x;
    return 0.5f * x * (1.f + tanhf(0.7978845608028654f * (x + 0.044715f * x3)));
}

__device__ __forceinline__ uint32_t f2tf32(float f) {
    uint32_t u;
    asm("cvt.rna.tf32.f32 %0, %1;" : "=r"(u) : "f"(f));
    return u;
}

__device__ __forceinline__ void mma_tf32(float& c0, float& c1, float& c2, float& c3,
                                         uint32_t a0, uint32_t a1, uint32_t a2, uint32_t a3,
                                         uint32_t b0, uint32_t b1) {
    asm volatile(
        "mma.sync.aligned.m16n8k8.row.col.f32.tf32.tf32.f32 "
        "{%0,%1,%2,%3}, {%4,%5,%6,%7}, {%8,%9}, {%0,%1,%2,%3};\n"
        : "+f"(c0), "+f"(c1), "+f"(c2), "+f"(c3)
        : "r"(a0), "r"(a1), "r"(a2), "r"(a3), "r"(b0), "r"(b1));
}

// block reduce of two values
__device__ __forceinline__ void blockReduce2(float& a, float& b) {
    __shared__ float sa[32], sb[32];
    __syncthreads();
    a = wsum(a); b = wsum(b);
    int w = threadIdx.x >> 5, l = threadIdx.x & 31;
    int nw = (blockDim.x + 31) >> 5;
    if (l == 0) { sa[w] = a; sb[w] = b; }
    __syncthreads();
    if (w == 0) {
        float x = (l < nw) ? sa[l] : 0.f;
        float y = (l < nw) ? sb[l] : 0.f;
        x = wsum(x); y = wsum(y);
        if (l == 0) { sa[0] = x; sb[0] = y; }
    }
    __syncthreads();
    a = sa[0]; b = sb[0];
}

// ---------------- embedding + LN ----------------
__global__ void embed_ln_kernel(const int* __restrict__ ids,
                                const float* __restrict__ we,
                                const float* __restrict__ pe,
                                const float* __restrict__ te,
                                const float* __restrict__ gam,
                                const float* __restrict__ bet) {
    int t = blockIdx.x;
    int sp = t % NB_S;
    int id = ids[t];
    __shared__ float buf[NB_D];
    float s1 = 0.f, s2 = 0.f;
    for (int d = threadIdx.x; d < NB_D; d += blockDim.x) {
        float v = we[(size_t)id * NB_D + d] + pe[sp * NB_D + d] + te[d];
        buf[d] = v; s1 += v; s2 += v * v;
    }
    blockReduce2(s1, s2);
    float mean = s1 * (1.f / NB_D);
    float inv = rsqrtf(s2 * (1.f / NB_D) - mean * mean + 1e-12f);
    for (int d = threadIdx.x; d < NB_D; d += blockDim.x)
        g_x[t * NB_D + d] = (buf[d] - mean) * inv * gam[d] + bet[d];
}

// ---------------- residual add + LN (x = LN(x + y)) ----------------
__global__ void add_ln_kernel(const float* __restrict__ gam,
                              const float* __restrict__ bet) {
    int t = blockIdx.x;
    __shared__ float buf[NB_D];
    float s1 = 0.f, s2 = 0.f;
    for (int d = threadIdx.x; d < NB_D; d += blockDim.x) {
        float v = g_x[t * NB_D + d] + g_y[t * NB_D + d];
        buf[d] = v; s1 += v; s2 += v * v;
    }
    blockReduce2(s1, s2);
    float mean = s1 * (1.f / NB_D);
    float inv = rsqrtf(s2 * (1.f / NB_D) - mean * mean + 1e-12f);
    for (int d = threadIdx.x; d < NB_D; d += blockDim.x)
        g_x[t * NB_D + d] = (buf[d] - mean) * inv * gam[d] + bet[d];
}

// ---------------- TF32 tensor-core GEMM ----------------
// C[M,N] = act(A[M,K] @ B[K,N] + bias). BM=128, BN=64, BK=16, 256 threads.
// 8 warps: 4 along M x 2 along N, each computing 32x32 via m16n8k8 mma.
// A smem stride 20 (== 4 mod 32) and B smem stride 72 (== 8 mod 32) make the
// per-quad fragment LDS patterns bank-conflict-free.
#define AST 20
#define BST 72
template <int ACT>
__global__ void __launch_bounds__(256)
tf32_gemm_kernel(const float* __restrict__ A,
                 const float* __restrict__ Bm,
                 const float* __restrict__ bias,
                 float* __restrict__ C,
                 int M, int N, int K) {
    __shared__ float As[2][128 * AST];
    __shared__ float Bs[2][16 * BST];

    int tid = threadIdx.x;
    int lane = tid & 31;
    int wid = tid >> 5;
    int wm = wid & 3;          // warp row 0..3 (32 rows each)
    int wn = wid >> 2;         // warp col 0..1 (32 cols each)
    int m0 = blockIdx.y * 128, n0 = blockIdx.x * 64;

    // staging indices
    int ar = tid >> 2, ac4 = (tid & 3) << 2;    // A: 64 rows x 4 k-floats (x2 row blocks)
    int br = tid >> 4, bc4 = (tid & 15) << 2;   // B: 16 rows x 4 n-floats

    const float* Ag = A + (size_t)(m0 + ar) * K + ac4;
    const float* Bg = Bm + (size_t)br * N + n0 + bc4;

    float acc[2][4][4];
#pragma unroll
    for (int i = 0; i < 2; i++)
#pragma unroll
        for (int j = 0; j < 4; j++)
#pragma unroll
            for (int e = 0; e < 4; e++) acc[i][j][e] = 0.f;

    const int nIter = K >> 4;

    // stage iter 0
    float4 pa0 = *(const float4*)(Ag);
    float4 pa1 = *(const float4*)(Ag + (size_t)64 * K);
    float4 pb0 = *(const float4*)(Bg);
    {
        float* as = As[0]; float* bs = Bs[0];
        as[ar * AST + ac4 + 0] = __uint_as_float(f2tf32(pa0.x));
        as[ar * AST + ac4 + 1] = __uint_as_float(f2tf32(pa0.y));
        as[ar * AST + ac4 + 2] = __uint_as_float(f2tf32(pa0.z));
        as[ar * AST + ac4 + 3] = __uint_as_float(f2tf32(pa0.w));
        as[(ar + 64) * AST + ac4 + 0] = __uint_as_float(f2tf32(pa1.x));
        as[(ar + 64) * AST + ac4 + 1] = __uint_as_float(f2tf32(pa1.y));
        as[(ar + 64) * AST + ac4 + 2] = __uint_as_float(f2tf32(pa1.z));
        as[(ar + 64) * AST + ac4 + 3] = __uint_as_float(f2tf32(pa1.w));
        bs[br * BST + bc4 + 0] = __uint_as_float(f2tf32(pb0.x));
        bs[br * BST + bc4 + 1] = __uint_as_float(f2tf32(pb0.y));
        bs[br * BST + bc4 + 2] = __uint_as_float(f2tf32(pb0.z));
        bs[br * BST + bc4 + 3] = __uint_as_float(f2tf32(pb0.w));
    }
    __syncthreads();

    for (int it = 0; it < nIter; it++) {
        int cur = it & 1;
        bool more = (it + 1 < nIter);
        if (more) {
            const float* a = Ag + (it + 1) * 16;
            pa0 = *(const float4*)(a);
            pa1 = *(const float4*)(a + (size_t)64 * K);
            pb0 = *(const float4*)(Bg + (size_t)(it + 1) * 16 * N);
        }

        // compute on buffer cur
        const float* as = As[cur];
        const float* bs = Bs[cur];
#pragma unroll
        for (int kk = 0; kk < 16; kk += 8) {
            uint32_t af[2][4], bf[4][2];
#pragma unroll
            for (int mt = 0; mt < 2; mt++) {
                int row = wm * 32 + mt * 16 + (lane >> 2);
                int col = kk + (lane & 3);
                af[mt][0] = __float_as_uint(as[row * AST + col]);
                af[mt][1] = __float_as_uint(as[(row + 8) * AST + col]);
                af[mt][2] = __float_as_uint(as[row * AST + col + 4]);
                af[mt][3] = __float_as_uint(as[(row + 8) * AST + col + 4]);
            }
#pragma unroll
            for (int nt = 0; nt < 4; nt++) {
                int col = wn * 32 + nt * 8 + (lane >> 2);
                bf[nt][0] = __float_as_uint(bs[(kk + (lane & 3)) * BST + col]);
                bf[nt][1] = __float_as_uint(bs[(kk + 4 + (lane & 3)) * BST + col]);
            }
#pragma unroll
            for (int mt = 0; mt < 2; mt++)
#pragma unroll
                for (int nt = 0; nt < 4; nt++)
                    mma_tf32(acc[mt][nt][0], acc[mt][nt][1], acc[mt][nt][2], acc[mt][nt][3],
                             af[mt][0], af[mt][1], af[mt][2], af[mt][3],
                             bf[nt][0], bf[nt][1]);
        }

        if (more) {
            float* asn = As[cur ^ 1]; float* bsn = Bs[cur ^ 1];
            asn[ar * AST + ac4 + 0] = __uint_as_float(f2tf32(pa0.x));
            asn[ar * AST + ac4 + 1] = __uint_as_float(f2tf32(pa0.y));
            asn[ar * AST + ac4 + 2] = __uint_as_float(f2tf32(pa0.z));
            asn[ar * AST + ac4 + 3] = __uint_as_float(f2tf32(pa0.w));
            asn[(ar + 64) * AST + ac4 + 0] = __uint_as_float(f2tf32(pa1.x));
            asn[(ar + 64) * AST + ac4 + 1] = __uint_as_float(f2tf32(pa1.y));
            asn[(ar + 64) * AST + ac4 + 2] = __uint_as_float(f2tf32(pa1.z));
            asn[(ar + 64) * AST + ac4 + 3] = __uint_as_float(f2tf32(pa1.w));
            bsn[br * BST + bc4 + 0] = __uint_as_float(f2tf32(pb0.x));
            bsn[br * BST + bc4 + 1] = __uint_as_float(f2tf32(pb0.y));
            bsn[br * BST + bc4 + 2] = __uint_as_float(f2tf32(pb0.z));
            bsn[br * BST + bc4 + 3] = __uint_as_float(f2tf32(pb0.w));
            __syncthreads();
        }
    }

    // epilogue
#pragma unroll
    for (int mt = 0; mt < 2; mt++) {
        int r0 = m0 + wm * 32 + mt * 16 + (lane >> 2);
#pragma unroll
        for (int nt = 0; nt < 4; nt++) {
            int c = n0 + wn * 32 + nt * 8 + ((lane & 3) << 1);
            float2 b2 = *(const float2*)(bias + c);
            float v0 = acc[mt][nt][0] + b2.x;
            float v1 = acc[mt][nt][1] + b2.y;
            float v2 = acc[mt][nt][2] + b2.x;
            float v3 = acc[mt][nt][3] + b2.y;
            if (ACT == 1) {
                v0 = gelu_tanh(v0); v1 = gelu_tanh(v1);
                v2 = gelu_tanh(v2); v3 = gelu_tanh(v3);
            }
            float2 o01 = make_float2(v0, v1);
            float2 o23 = make_float2(v2, v3);
            *(float2*)(C + (size_t)r0 * N + c) = o01;
            *(float2*)(C + (size_t)(r0 + 8) * N + c) = o23;
        }
    }
}

// ---------------- beta = sigmoid(x @ Wb) * mask ----------------
__global__ void beta_kernel(const float* __restrict__ Wb,
                            const int* __restrict__ amask) {
    int t = blockIdx.x;
    int w = threadIdx.x >> 5, l = threadIdx.x & 31;
    const float* xr = g_x + (size_t)t * NB_D;
    float s = 0.f;
    for (int d = l; d < NB_D; d += 32) s += xr[d] * Wb[d * NB_H + w];
    s = wsum(s);
    if (l == 0)
        g_beta[t * NB_H + w] = (float)amask[t] * (1.f / (1.f + expf(-s)));
}

// ---------------- per-(token,head) L2 normalize q and k ----------------
__global__ void qknorm_kernel() {
    int gw = blockIdx.x * 8 + (threadIdx.x >> 5);
    int l = threadIdx.x & 31;
    int t = gw / NB_H, h = gw % NB_H;
    int idx = t * NB_D + h * NB_HD + l;
    float qv = g_q[idx];
    float s = wsum(qv * qv);
    g_q[idx] = qv / (sqrtf(s) + 1e-6f);
    float kv = g_k[idx];
    s = wsum(kv * kv);
    g_k[idx] = kv / (sqrtf(s) + 1e-6f);
}

// ---------------- hierarchical delta-rule scan ----------------
__global__ void scan_kernel(const float* __restrict__ dfast,
                            const float* __restrict__ dslow,
                            const float* __restrict__ mixl) {
    int gw = blockIdx.x * (blockDim.x >> 5) + (threadIdx.x >> 5);
    int l = threadIdx.x & 31;
    int vcol = gw & 31;
    int bh = gw >> 5;
    int h = bh % NB_H;
    int b = bh / NB_H;

    float af = sigm(dfast[h]);
    float as_ = sigm(dslow[h]);
    float g = sigm(mixl[h]);
    float gi = 1.f - g;

    int rb = b * NB_S * NB_D + h * NB_HD;
    int bb = b * NB_S * NB_H + h;
    float Sf = 0.f, Ss = 0.f;

    for (int t = 0; t < NB_S; t++, rb += NB_D, bb += NB_H) {
        float kt = g_k[rb + l];
        float qt = g_q[rb + l];
        float vt = g_v[rb + vcol];
        float bt = g_beta[bb];
        float pf = wsum(Sf * kt);
        float ps = wsum(Ss * kt);
        float bk = bt * kt;
        Sf = af * Sf + bk * (vt - pf);
        Ss = as_ * Ss + bk * (vt - ps);
        float oc = wsum(qt * (g * Sf + gi * Ss));
        if (l == 0) g_o[rb + vcol] = oc;
    }
}

// ---------------- masked mean pool + L2 normalize ----------------
__global__ void pool_kernel(const int* __restrict__ amask,
                            float* __restrict__ out) {
    int b = blockIdx.x, d = threadIdx.x;
    float sum = 0.f, ms = 0.f;
    for (int s = 0; s < NB_S; s++) {
        float m = (float)amask[b * NB_S + s];
        sum += g_x[(size_t)(b * NB_S + s) * NB_D + d] * m;
        ms += m;
    }
    float pooled = sum / fmaxf(ms, 1e-9f);
    float sq = pooled * pooled;
    float dummy = 0.f;
    blockReduce2(sq, dummy);
    out[b * NB_D + d] = pooled * rsqrtf(sq);
}

// ---------------- launch ----------------
extern "C" void kernel_launch(void* const* d_in, const int* in_sizes, int n_in,
                              void* d_out, int out_size) {
    const int*   ids   = (const int*)d_in[0];
    const int*   amask = (const int*)d_in[1];
    const float* we    = (const float*)d_in[2];
    const float* pe    = (const float*)d_in[3];
    const float* te    = (const float*)d_in[4];
    const float* elg   = (const float*)d_in[5];
    const float* elb   = (const float*)d_in[6];
    const float* Wq    = (const float*)d_in[7];
    const float* bq    = (const float*)d_in[8];
    const float* Wk    = (const float*)d_in[9];
    const float* bk    = (const float*)d_in[10];
    const float* Wv    = (const float*)d_in[11];
    const float* bv    = (const float*)d_in[12];
    const float* Wb    = (const float*)d_in[13];
    const float* dfast = (const float*)d_in[14];
    const float* dslow = (const float*)d_in[15];
    const float* mixl  = (const float*)d_in[16];
    const float* Wo    = (const float*)d_in[17];
    const float* bo    = (const float*)d_in[18];
    const float* alg   = (const float*)d_in[19];
    const float* alb   = (const float*)d_in[20];
    const float* W1    = (const float*)d_in[21];
    const float* b1    = (const float*)d_in[22];
    const float* W2    = (const float*)d_in[23];
    const float* b2    = (const float*)d_in[24];
    const float* flg   = (const float*)d_in[25];
    const float* flb   = (const float*)d_in[26];
    float* out = (float*)d_out;

    float *p_x, *p_q, *p_k, *p_v, *p_o, *p_y, *p_h;
    cudaGetSymbolAddress((void**)&p_x, g_x);
    cudaGetSymbolAddress((void**)&p_q, g_q);
    cudaGetSymbolAddress((void**)&p_k, g_k);
    cudaGetSymbolAddress((void**)&p_v, g_v);
    cudaGetSymbolAddress((void**)&p_o, g_o);
    cudaGetSymbolAddress((void**)&p_y, g_y);
    cudaGetSymbolAddress((void**)&p_h, g_h);

    embed_ln_kernel<<<NB_T, 128>>>(ids, we, pe, te, elg, elb);

    dim3 gD(NB_D / 64, NB_T / 128);    // N=384
    dim3 gF(NB_FF / 64, NB_T / 128);   // N=1536

    for (int l = 0; l < NB_L; l++) {
        const float* wq = Wq + (size_t)l * NB_D * NB_D;
        const float* wk = Wk + (size_t)l * NB_D * NB_D;
        const float* wv = Wv + (size_t)l * NB_D * NB_D;
        const float* wo = Wo + (size_t)l * NB_D * NB_D;
        const float* w1 = W1 + (size_t)l * NB_D * NB_FF;
        const float* w2 = W2 + (size_t)l * NB_FF * NB_D;

        tf32_gemm_kernel<0><<<gD, 256>>>(p_x, wq, bq + l * NB_D, p_q, NB_T, NB_D, NB_D);
        tf32_gemm_kernel<0><<<gD, 256>>>(p_x, wk, bk + l * NB_D, p_k, NB_T, NB_D, NB_D);
        tf32_gemm_kernel<0><<<gD, 256>>>(p_x, wv, bv + l * NB_D, p_v, NB_T, NB_D, NB_D);

        beta_kernel<<<NB_T, NB_H * 32>>>(Wb + (size_t)l * NB_D * NB_H, amask);
        qknorm_kernel<<<(NB_T * NB_H) / 8, 256>>>();
        scan_kernel<<<(NB_B * NB_H * NB_HD) / 4, 128>>>(
            dfast + l * NB_H, dslow + l * NB_H, mixl + l * NB_H);

        tf32_gemm_kernel<0><<<gD, 256>>>(p_o, wo, bo + l * NB_D, p_y, NB_T, NB_D, NB_D);
        add_ln_kernel<<<NB_T, 128>>>(alg + l * NB_D, alb + l * NB_D);

        tf32_gemm_kernel<1><<<gF, 256>>>(p_x, w1, b1 + l * NB_FF, p_h, NB_T, NB_FF, NB_D);
        tf32_gemm_kernel<0><<<gD, 256>>>(p_h, w2, b2 + l * NB_D, p_y, NB_T, NB_D, NB_FF);
        add_ln_kernel<<<NB_T, 128>>>(flg + l * NB_D, flb + l * NB_D);
    }

    pool_kernel<<<NB_B, NB_D>>>(amask, out);
}

// round 3
// speedup vs baseline: 1.9116x; 1.1103x over previous
#include <cuda_runtime.h>
#include <math.h>
#include <stdint.h>

// ---------------- model dims ----------------
#define NB_B 32
#define NB_S 512
#define NB_T (NB_B*NB_S)      // 16384 tokens
#define NB_D 384
#define NB_H 12
#define NB_HD 32
#define NB_FF 1536
#define NB_L 6

// ---------------- device scratch (allocation-free) ----------------
__device__ float g_x[NB_T*NB_D];      // activations
__device__ float g_q[NB_T*NB_D];
__device__ float g_k[NB_T*NB_D];
__device__ float g_v[NB_T*NB_D];
__device__ float g_o[NB_T*NB_D];      // deltanet output
__device__ float g_y[NB_T*NB_D];      // gemm output (Wo / W2)
__device__ float g_h[NB_T*NB_FF];     // ffn hidden
__device__ float g_beta[NB_T*NB_H];

// ---------------- helpers ----------------
__device__ __forceinline__ float wsum(float v) {
#pragma unroll
    for (int o = 16; o > 0; o >>= 1) v += __shfl_xor_sync(0xffffffffu, v, o);
    return v;
}

__device__ __forceinline__ float sigm(float x) { return 1.f / (1.f + expf(-x)); }

__device__ __forceinline__ float gelu_tanh(float x) {
    float x3 = x * x * x;
    return 0.5f * x * (1.f + tanhf(0.7978845608028654f * (x + 0.044715f * x3)));
}

__device__ __forceinline__ uint32_t f2tf32(float f) {
    uint32_t u;
    asm("cvt.rna.tf32.f32 %0, %1;" : "=r"(u) : "f"(f));
    return u;
}

__device__ __forceinline__ void mma_tf32(float& c0, float& c1, float& c2, float& c3,
                                         uint32_t a0, uint32_t a1, uint32_t a2, uint32_t a3,
                                         uint32_t b0, uint32_t b1) {
    asm volatile(
        "mma.sync.aligned.m16n8k8.row.col.f32.tf32.tf32.f32 "
        "{%0,%1,%2,%3}, {%4,%5,%6,%7}, {%8,%9}, {%0,%1,%2,%3};\n"
        : "+f"(c0), "+f"(c1), "+f"(c2), "+f"(c3)
        : "r"(a0), "r"(a1), "r"(a2), "r"(a3), "r"(b0), "r"(b1));
}

// block reduce of two values
__device__ __forceinline__ void blockReduce2(float& a, float& b) {
    __shared__ float sa[32], sb[32];
    __syncthreads();
    a = wsum(a); b = wsum(b);
    int w = threadIdx.x >> 5, l = threadIdx.x & 31;
    int nw = (blockDim.x + 31) >> 5;
    if (l == 0) { sa[w] = a; sb[w] = b; }
    __syncthreads();
    if (w == 0) {
        float x = (l < nw) ? sa[l] : 0.f;
        float y = (l < nw) ? sb[l] : 0.f;
        x = wsum(x); y = wsum(y);
        if (l == 0) { sa[0] = x; sb[0] = y; }
    }
    __syncthreads();
    a = sa[0]; b = sb[0];
}

// ---------------- embedding + LN ----------------
__global__ void embed_ln_kernel(const int* __restrict__ ids,
                                const float* __restrict__ we,
                                const float* __restrict__ pe,
                                const float* __restrict__ te,
                                const float* __restrict__ gam,
                                const float* __restrict__ bet) {
    int t = blockIdx.x;
    int sp = t % NB_S;
    int id = ids[t];
    __shared__ float buf[NB_D];
    float s1 = 0.f, s2 = 0.f;
    for (int d = threadIdx.x; d < NB_D; d += blockDim.x) {
        float v = we[(size_t)id * NB_D + d] + pe[sp * NB_D + d] + te[d];
        buf[d] = v; s1 += v; s2 += v * v;
    }
    blockReduce2(s1, s2);
    float mean = s1 * (1.f / NB_D);
    float inv = rsqrtf(s2 * (1.f / NB_D) - mean * mean + 1e-12f);
    for (int d = threadIdx.x; d < NB_D; d += blockDim.x)
        g_x[t * NB_D + d] = (buf[d] - mean) * inv * gam[d] + bet[d];
}

// ---------------- residual add + LN (x = LN(x + y)) ----------------
__global__ void add_ln_kernel(const float* __restrict__ gam,
                              const float* __restrict__ bet) {
    int t = blockIdx.x;
    __shared__ float buf[NB_D];
    float s1 = 0.f, s2 = 0.f;
    for (int d = threadIdx.x; d < NB_D; d += blockDim.x) {
        float v = g_x[t * NB_D + d] + g_y[t * NB_D + d];
        buf[d] = v; s1 += v; s2 += v * v;
    }
    blockReduce2(s1, s2);
    float mean = s1 * (1.f / NB_D);
    float inv = rsqrtf(s2 * (1.f / NB_D) - mean * mean + 1e-12f);
    for (int d = threadIdx.x; d < NB_D; d += blockDim.x)
        g_x[t * NB_D + d] = (buf[d] - mean) * inv * gam[d] + bet[d];
}

// ---------------- TF32 tensor-core GEMM ----------------
// C[M,N] = act(A[M,K] @ B[K,N] + bias). BM=128, BN=64, BK=16, 256 threads.
#define AST 20
#define BST 72
template <int ACT>
__global__ void __launch_bounds__(256)
tf32_gemm_kernel(const float* __restrict__ A,
                 const float* __restrict__ Bm,
                 const float* __restrict__ bias,
                 float* __restrict__ C,
                 int M, int N, int K) {
    __shared__ float As[2][128 * AST];
    __shared__ float Bs[2][16 * BST];

    int tid = threadIdx.x;
    int lane = tid & 31;
    int wid = tid >> 5;
    int wm = wid & 3;
    int wn = wid >> 2;
    int m0 = blockIdx.y * 128, n0 = blockIdx.x * 64;

    int ar = tid >> 2, ac4 = (tid & 3) << 2;
    int br = tid >> 4, bc4 = (tid & 15) << 2;

    const float* Ag = A + (size_t)(m0 + ar) * K + ac4;
    const float* Bg = Bm + (size_t)br * N + n0 + bc4;

    float acc[2][4][4];
#pragma unroll
    for (int i = 0; i < 2; i++)
#pragma unroll
        for (int j = 0; j < 4; j++)
#pragma unroll
            for (int e = 0; e < 4; e++) acc[i][j][e] = 0.f;

    const int nIter = K >> 4;

    float4 pa0 = *(const float4*)(Ag);
    float4 pa1 = *(const float4*)(Ag + (size_t)64 * K);
    float4 pb0 = *(const float4*)(Bg);
    {
        float* as = As[0]; float* bs = Bs[0];
        as[ar * AST + ac4 + 0] = __uint_as_float(f2tf32(pa0.x));
        as[ar * AST + ac4 + 1] = __uint_as_float(f2tf32(pa0.y));
        as[ar * AST + ac4 + 2] = __uint_as_float(f2tf32(pa0.z));
        as[ar * AST + ac4 + 3] = __uint_as_float(f2tf32(pa0.w));
        as[(ar + 64) * AST + ac4 + 0] = __uint_as_float(f2tf32(pa1.x));
        as[(ar + 64) * AST + ac4 + 1] = __uint_as_float(f2tf32(pa1.y));
        as[(ar + 64) * AST + ac4 + 2] = __uint_as_float(f2tf32(pa1.z));
        as[(ar + 64) * AST + ac4 + 3] = __uint_as_float(f2tf32(pa1.w));
        bs[br * BST + bc4 + 0] = __uint_as_float(f2tf32(pb0.x));
        bs[br * BST + bc4 + 1] = __uint_as_float(f2tf32(pb0.y));
        bs[br * BST + bc4 + 2] = __uint_as_float(f2tf32(pb0.z));
        bs[br * BST + bc4 + 3] = __uint_as_float(f2tf32(pb0.w));
    }
    __syncthreads();

    for (int it = 0; it < nIter; it++) {
        int cur = it & 1;
        bool more = (it + 1 < nIter);
        if (more) {
            const float* a = Ag + (it + 1) * 16;
            pa0 = *(const float4*)(a);
            pa1 = *(const float4*)(a + (size_t)64 * K);
            pb0 = *(const float4*)(Bg + (size_t)(it + 1) * 16 * N);
        }

        const float* as = As[cur];
        const float* bs = Bs[cur];
#pragma unroll
        for (int kk = 0; kk < 16; kk += 8) {
            uint32_t af[2][4], bf[4][2];
#pragma unroll
            for (int mt = 0; mt < 2; mt++) {
                int row = wm * 32 + mt * 16 + (lane >> 2);
                int col = kk + (lane & 3);
                af[mt][0] = __float_as_uint(as[row * AST + col]);
                af[mt][1] = __float_as_uint(as[(row + 8) * AST + col]);
                af[mt][2] = __float_as_uint(as[row * AST + col + 4]);
                af[mt][3] = __float_as_uint(as[(row + 8) * AST + col + 4]);
            }
#pragma unroll
            for (int nt = 0; nt < 4; nt++) {
                int col = wn * 32 + nt * 8 + (lane >> 2);
                bf[nt][0] = __float_as_uint(bs[(kk + (lane & 3)) * BST + col]);
                bf[nt][1] = __float_as_uint(bs[(kk + 4 + (lane & 3)) * BST + col]);
            }
#pragma unroll
            for (int mt = 0; mt < 2; mt++)
#pragma unroll
                for (int nt = 0; nt < 4; nt++)
                    mma_tf32(acc[mt][nt][0], acc[mt][nt][1], acc[mt][nt][2], acc[mt][nt][3],
                             af[mt][0], af[mt][1], af[mt][2], af[mt][3],
                             bf[nt][0], bf[nt][1]);
        }

        if (more) {
            float* asn = As[cur ^ 1]; float* bsn = Bs[cur ^ 1];
            asn[ar * AST + ac4 + 0] = __uint_as_float(f2tf32(pa0.x));
            asn[ar * AST + ac4 + 1] = __uint_as_float(f2tf32(pa0.y));
            asn[ar * AST + ac4 + 2] = __uint_as_float(f2tf32(pa0.z));
            asn[ar * AST + ac4 + 3] = __uint_as_float(f2tf32(pa0.w));
            asn[(ar + 64) * AST + ac4 + 0] = __uint_as_float(f2tf32(pa1.x));
            asn[(ar + 64) * AST + ac4 + 1] = __uint_as_float(f2tf32(pa1.y));
            asn[(ar + 64) * AST + ac4 + 2] = __uint_as_float(f2tf32(pa1.z));
            asn[(ar + 64) * AST + ac4 + 3] = __uint_as_float(f2tf32(pa1.w));
            bsn[br * BST + bc4 + 0] = __uint_as_float(f2tf32(pb0.x));
            bsn[br * BST + bc4 + 1] = __uint_as_float(f2tf32(pb0.y));
            bsn[br * BST + bc4 + 2] = __uint_as_float(f2tf32(pb0.z));
            bsn[br * BST + bc4 + 3] = __uint_as_float(f2tf32(pb0.w));
            __syncthreads();
        }
    }

#pragma unroll
    for (int mt = 0; mt < 2; mt++) {
        int r0 = m0 + wm * 32 + mt * 16 + (lane >> 2);
#pragma unroll
        for (int nt = 0; nt < 4; nt++) {
            int c = n0 + wn * 32 + nt * 8 + ((lane & 3) << 1);
            float2 b2 = *(const float2*)(bias + c);
            float v0 = acc[mt][nt][0] + b2.x;
            float v1 = acc[mt][nt][1] + b2.y;
            float v2 = acc[mt][nt][2] + b2.x;
            float v3 = acc[mt][nt][3] + b2.y;
            if (ACT == 1) {
                v0 = gelu_tanh(v0); v1 = gelu_tanh(v1);
                v2 = gelu_tanh(v2); v3 = gelu_tanh(v3);
            }
            float2 o01 = make_float2(v0, v1);
            float2 o23 = make_float2(v2, v3);
            *(float2*)(C + (size_t)r0 * N + c) = o01;
            *(float2*)(C + (size_t)(r0 + 8) * N + c) = o23;
        }
    }
}

// ---------------- beta = sigmoid(x @ Wb) * mask ----------------
__global__ void beta_kernel(const float* __restrict__ Wb,
                            const int* __restrict__ amask) {
    int t = blockIdx.x;
    int w = threadIdx.x >> 5, l = threadIdx.x & 31;
    const float* xr = g_x + (size_t)t * NB_D;
    float s = 0.f;
    for (int d = l; d < NB_D; d += 32) s += xr[d] * Wb[d * NB_H + w];
    s = wsum(s);
    if (l == 0)
        g_beta[t * NB_H + w] = (float)amask[t] * (1.f / (1.f + expf(-s)));
}

// ---------------- hierarchical delta-rule scan (lane = v-column) ----------------
// One warp per (b,h). Lane v holds full state columns Sf[k][v], Ss[k][v] in
// registers (k = 0..31). Per step, kt[k]/qt[k] are broadcast with independent
// shuffles; the two delta-rule predictions and the output become pure local
// register FMAs — no chained warp reductions. qk L2-normalization is fused.
__global__ void __launch_bounds__(128)
scan_kernel(const float* __restrict__ dfast,
            const float* __restrict__ dslow,
            const float* __restrict__ mixl) {
    int bh = blockIdx.x * 4 + (threadIdx.x >> 5);
    int l = threadIdx.x & 31;
    int h = bh % NB_H;
    int b = bh / NB_H;

    float af = sigm(dfast[h]);
    float as_ = sigm(dslow[h]);
    float g = sigm(mixl[h]);
    float gi = 1.f - g;

    float Sf[32], Ss[32];
#pragma unroll
    for (int k = 0; k < 32; k++) { Sf[k] = 0.f; Ss[k] = 0.f; }

    int rb = b * NB_S * NB_D + h * NB_HD;
    int bb = b * NB_S * NB_H + h;

    for (int t = 0; t < NB_S; t++, rb += NB_D, bb += NB_H) {
        float kt = g_k[rb + l];
        float qt = g_q[rb + l];
        float vt = g_v[rb + l];
        float bt = g_beta[bb];

        // fused L2 norms over the head dim
        float nk = wsum(kt * kt);
        kt = kt / (sqrtf(nk) + 1e-6f);
        float nq = wsum(qt * qt);
        qt = qt / (sqrtf(nq) + 1e-6f);

        // broadcast kt and accumulate predictions locally (per-v)
        float kk[32];
        float pf0 = 0.f, pf1 = 0.f, ps0 = 0.f, ps1 = 0.f;
#pragma unroll
        for (int k = 0; k < 32; k += 2) {
            kk[k]     = __shfl_sync(0xffffffffu, kt, k);
            kk[k + 1] = __shfl_sync(0xffffffffu, kt, k + 1);
            pf0 += Sf[k] * kk[k];     ps0 += Ss[k] * kk[k];
            pf1 += Sf[k + 1] * kk[k + 1]; ps1 += Ss[k + 1] * kk[k + 1];
        }
        float pf = pf0 + pf1, ps = ps0 + ps1;

        float cf = bt * (vt - pf);
        float cs = bt * (vt - ps);

        float o0 = 0.f, o1 = 0.f;
#pragma unroll
        for (int k = 0; k < 32; k += 2) {
            float qk0 = __shfl_sync(0xffffffffu, qt, k);
            float qk1 = __shfl_sync(0xffffffffu, qt, k + 1);
            Sf[k]     = af * Sf[k]     + kk[k] * cf;
            Ss[k]     = as_ * Ss[k]    + kk[k] * cs;
            Sf[k + 1] = af * Sf[k + 1] + kk[k + 1] * cf;
            Ss[k + 1] = as_ * Ss[k + 1] + kk[k + 1] * cs;
            o0 += qk0 * (g * Sf[k] + gi * Ss[k]);
            o1 += qk1 * (g * Sf[k + 1] + gi * Ss[k + 1]);
        }
        g_o[rb + l] = o0 + o1;
    }
}

// ---------------- masked mean pool + L2 normalize ----------------
__global__ void pool_kernel(const int* __restrict__ amask,
                            float* __restrict__ out) {
    int b = blockIdx.x, d = threadIdx.x;
    float sum = 0.f, ms = 0.f;
    for (int s = 0; s < NB_S; s++) {
        float m = (float)amask[b * NB_S + s];
        sum += g_x[(size_t)(b * NB_S + s) * NB_D + d] * m;
        ms += m;
    }
    float pooled = sum / fmaxf(ms, 1e-9f);
    float sq = pooled * pooled;
    float dummy = 0.f;
    blockReduce2(sq, dummy);
    out[b * NB_D + d] = pooled * rsqrtf(sq);
}

// ---------------- launch ----------------
extern "C" void kernel_launch(void* const* d_in, const int* in_sizes, int n_in,
                              void* d_out, int out_size) {
    const int*   ids   = (const int*)d_in[0];
    const int*   amask = (const int*)d_in[1];
    const float* we    = (const float*)d_in[2];
    const float* pe    = (const float*)d_in[3];
    const float* te    = (const float*)d_in[4];
    const float* elg   = (const float*)d_in[5];
    const float* elb   = (const float*)d_in[6];
    const float* Wq    = (const float*)d_in[7];
    const float* bq    = (const float*)d_in[8];
    const float* Wk    = (const float*)d_in[9];
    const float* bk    = (const float*)d_in[10];
    const float* Wv    = (const float*)d_in[11];
    const float* bv    = (const float*)d_in[12];
    const float* Wb    = (const float*)d_in[13];
    const float* dfast = (const float*)d_in[14];
    const float* dslow = (const float*)d_in[15];
    const float* mixl  = (const float*)d_in[16];
    const float* Wo    = (const float*)d_in[17];
    const float* bo    = (const float*)d_in[18];
    const float* alg   = (const float*)d_in[19];
    const float* alb   = (const float*)d_in[20];
    const float* W1    = (const float*)d_in[21];
    const float* b1    = (const float*)d_in[22];
    const float* W2    = (const float*)d_in[23];
    const float* b2    = (const float*)d_in[24];
    const float* flg   = (const float*)d_in[25];
    const float* flb   = (const float*)d_in[26];
    float* out = (float*)d_out;

    float *p_x, *p_q, *p_k, *p_v, *p_o, *p_y, *p_h;
    cudaGetSymbolAddress((void**)&p_x, g_x);
    cudaGetSymbolAddress((void**)&p_q, g_q);
    cudaGetSymbolAddress((void**)&p_k, g_k);
    cudaGetSymbolAddress((void**)&p_v, g_v);
    cudaGetSymbolAddress((void**)&p_o, g_o);
    cudaGetSymbolAddress((void**)&p_y, g_y);
    cudaGetSymbolAddress((void**)&p_h, g_h);

    embed_ln_kernel<<<NB_T, 128>>>(ids, we, pe, te, elg, elb);

    dim3 gD(NB_D / 64, NB_T / 128);    // N=384
    dim3 gF(NB_FF / 64, NB_T / 128);   // N=1536

    for (int l = 0; l < NB_L; l++) {
        const float* wq = Wq + (size_t)l * NB_D * NB_D;
        const float* wk = Wk + (size_t)l * NB_D * NB_D;
        const float* wv = Wv + (size_t)l * NB_D * NB_D;
        const float* wo = Wo + (size_t)l * NB_D * NB_D;
        const float* w1 = W1 + (size_t)l * NB_D * NB_FF;
        const float* w2 = W2 + (size_t)l * NB_FF * NB_D;

        tf32_gemm_kernel<0><<<gD, 256>>>(p_x, wq, bq + l * NB_D, p_q, NB_T, NB_D, NB_D);
        tf32_gemm_kernel<0><<<gD, 256>>>(p_x, wk, bk + l * NB_D, p_k, NB_T, NB_D, NB_D);
        tf32_gemm_kernel<0><<<gD, 256>>>(p_x, wv, bv + l * NB_D, p_v, NB_T, NB_D, NB_D);

        beta_kernel<<<NB_T, NB_H * 32>>>(Wb + (size_t)l * NB_D * NB_H, amask);
        scan_kernel<<<(NB_B * NB_H) / 4, 128>>>(
            dfast + l * NB_H, dslow + l * NB_H, mixl + l * NB_H);

        tf32_gemm_kernel<0><<<gD, 256>>>(p_o, wo, bo + l * NB_D, p_y, NB_T, NB_D, NB_D);
        add_ln_kernel<<<NB_T, 128>>>(alg + l * NB_D, alb + l * NB_D);

        tf32_gemm_kernel<1><<<gF, 256>>>(p_x, w1, b1 + l * NB_FF, p_h, NB_T, NB_FF, NB_D);
        tf32_gemm_kernel<0><<<gD, 256>>>(p_h, w2, b2 + l * NB_D, p_y, NB_T, NB_D, NB_FF);
        add_ln_kernel<<<NB_T, 128>>>(flg + l * NB_D, flb + l * NB_D);
    }

    pool_kernel<<<NB_B, NB_D>>>(amask, out);
}

// round 4
// speedup vs baseline: 2.5982x; 1.3592x over previous
#include <cuda_runtime.h>
#include <cuda_fp16.h>
#include <math.h>
#include <stdint.h>

// ---------------- model dims ----------------
#define NB_B 32
#define NB_S 512
#define NB_T (NB_B*NB_S)      // 16384 tokens
#define NB_D 384
#define NB_H 12
#define NB_HD 32
#define NB_FF 1536
#define NB_L 6

// ---------------- device scratch (allocation-free) ----------------
__device__ float g_x[NB_T*NB_D];      // activations
__device__ float g_q[NB_T*NB_D];
__device__ float g_k[NB_T*NB_D];
__device__ float g_v[NB_T*NB_D];
__device__ float g_o[NB_T*NB_D];      // deltanet output
__device__ float g_y[NB_T*NB_D];      // gemm output (Wo / W2)
__device__ float g_h[NB_T*NB_FF];     // ffn hidden
__device__ float g_beta[NB_T*NB_H];

// ---------------- helpers ----------------
__device__ __forceinline__ float wsum(float v) {
#pragma unroll
    for (int o = 16; o > 0; o >>= 1) v += __shfl_xor_sync(0xffffffffu, v, o);
    return v;
}

__device__ __forceinline__ float sigm(float x) { return 1.f / (1.f + expf(-x)); }

__device__ __forceinline__ float gelu_tanh(float x) {
    float x3 = x * x * x;
    return 0.5f * x * (1.f + tanhf(0.7978845608028654f * (x + 0.044715f * x3)));
}

__device__ __forceinline__ uint32_t smem_u32(const void* p) {
    return (uint32_t)__cvta_generic_to_shared(p);
}

__device__ __forceinline__ void ldm_x4(uint32_t& r0, uint32_t& r1, uint32_t& r2, uint32_t& r3,
                                       uint32_t addr) {
    asm volatile("ldmatrix.sync.aligned.m8n8.x4.shared.b16 {%0,%1,%2,%3}, [%4];"
                 : "=r"(r0), "=r"(r1), "=r"(r2), "=r"(r3) : "r"(addr));
}

__device__ __forceinline__ void ldm_x4_t(uint32_t& r0, uint32_t& r1, uint32_t& r2, uint32_t& r3,
                                         uint32_t addr) {
    asm volatile("ldmatrix.sync.aligned.m8n8.x4.trans.shared.b16 {%0,%1,%2,%3}, [%4];"
                 : "=r"(r0), "=r"(r1), "=r"(r2), "=r"(r3) : "r"(addr));
}

__device__ __forceinline__ void mma_f16(float& c0, float& c1, float& c2, float& c3,
                                        uint32_t a0, uint32_t a1, uint32_t a2, uint32_t a3,
                                        uint32_t b0, uint32_t b1) {
    asm volatile(
        "mma.sync.aligned.m16n8k16.row.col.f32.f16.f16.f32 "
        "{%0,%1,%2,%3}, {%4,%5,%6,%7}, {%8,%9}, {%0,%1,%2,%3};\n"
        : "+f"(c0), "+f"(c1), "+f"(c2), "+f"(c3)
        : "r"(a0), "r"(a1), "r"(a2), "r"(a3), "r"(b0), "r"(b1));
}

__device__ __forceinline__ uint2 f4_to_h4(float4 v) {
    __half2 h0 = __floats2half2_rn(v.x, v.y);
    __half2 h1 = __floats2half2_rn(v.z, v.w);
    uint2 r;
    r.x = *(uint32_t*)&h0;
    r.y = *(uint32_t*)&h1;
    return r;
}

// block reduce of two values
__device__ __forceinline__ void blockReduce2(float& a, float& b) {
    __shared__ float sa[32], sb[32];
    __syncthreads();
    a = wsum(a); b = wsum(b);
    int w = threadIdx.x >> 5, l = threadIdx.x & 31;
    int nw = (blockDim.x + 31) >> 5;
    if (l == 0) { sa[w] = a; sb[w] = b; }
    __syncthreads();
    if (w == 0) {
        float x = (l < nw) ? sa[l] : 0.f;
        float y = (l < nw) ? sb[l] : 0.f;
        x = wsum(x); y = wsum(y);
        if (l == 0) { sa[0] = x; sb[0] = y; }
    }
    __syncthreads();
    a = sa[0]; b = sb[0];
}

// ---------------- embedding + LN ----------------
__global__ void embed_ln_kernel(const int* __restrict__ ids,
                                const float* __restrict__ we,
                                const float* __restrict__ pe,
                                const float* __restrict__ te,
                                const float* __restrict__ gam,
                                const float* __restrict__ bet) {
    int t = blockIdx.x;
    int sp = t % NB_S;
    int id = ids[t];
    __shared__ float buf[NB_D];
    float s1 = 0.f, s2 = 0.f;
    for (int d = threadIdx.x; d < NB_D; d += blockDim.x) {
        float v = we[(size_t)id * NB_D + d] + pe[sp * NB_D + d] + te[d];
        buf[d] = v; s1 += v; s2 += v * v;
    }
    blockReduce2(s1, s2);
    float mean = s1 * (1.f / NB_D);
    float inv = rsqrtf(s2 * (1.f / NB_D) - mean * mean + 1e-12f);
    for (int d = threadIdx.x; d < NB_D; d += blockDim.x)
        g_x[t * NB_D + d] = (buf[d] - mean) * inv * gam[d] + bet[d];
}

// ---------------- residual add + LN (x = LN(x + y)) ----------------
__global__ void add_ln_kernel(const float* __restrict__ gam,
                              const float* __restrict__ bet) {
    int t = blockIdx.x;
    __shared__ float buf[NB_D];
    float s1 = 0.f, s2 = 0.f;
    for (int d = threadIdx.x; d < NB_D; d += blockDim.x) {
        float v = g_x[t * NB_D + d] + g_y[t * NB_D + d];
        buf[d] = v; s1 += v; s2 += v * v;
    }
    blockReduce2(s1, s2);
    float mean = s1 * (1.f / NB_D);
    float inv = rsqrtf(s2 * (1.f / NB_D) - mean * mean + 1e-12f);
    for (int d = threadIdx.x; d < NB_D; d += blockDim.x)
        g_x[t * NB_D + d] = (buf[d] - mean) * inv * gam[d] + bet[d];
}

// ---------------- FP16 tensor-core GEMM with ldmatrix ----------------
// C[M,Nsub] = act(A[M,K] @ Bsel[K,Nsub] + bias_sel). Up to 3 output matrices
// selected by blockIdx.x (fused QKV). BM=128, BN=64, BK=32, 256 threads,
// 8 warps (4 along M x 2 along N), each warp computes 32x32 via m16n8k16.
// A smem stride 40 halves (80B), B smem stride 72 halves (144B): 16B-aligned
// rows with distinct mod-128 phases -> conflict-free ldmatrix.
#define ASTH 40
#define BSTH 72
template <int ACT>
__global__ void __launch_bounds__(256)
h16_gemm_kernel(const float* __restrict__ A,
                const float* __restrict__ B0, const float* __restrict__ B1,
                const float* __restrict__ B2,
                const float* __restrict__ bias0, const float* __restrict__ bias1,
                const float* __restrict__ bias2,
                float* __restrict__ C0, float* __restrict__ C1, float* __restrict__ C2,
                int M, int Nsub, int K, int blocksPerSub) {
    __shared__ __half Ash[2][128 * ASTH];
    __shared__ __half Bsh[2][32 * BSTH];

    int tid = threadIdx.x;
    int lane = tid & 31;
    int wid = tid >> 5;
    int wm = wid & 3;          // 0..3, 32 rows each
    int wn = wid >> 2;         // 0..1, 32 cols each

    int sel = blockIdx.x / blocksPerSub;
    int n0 = (blockIdx.x % blocksPerSub) * 64;
    int m0 = blockIdx.y * 128;

    const float* Bm  = (sel == 0) ? B0 : (sel == 1) ? B1 : B2;
    const float* bia = (sel == 0) ? bias0 : (sel == 1) ? bias1 : bias2;
    float* C         = (sel == 0) ? C0 : (sel == 1) ? C1 : C2;

    // staging indices
    int arow = tid >> 1, akg = (tid & 1) << 4;     // 128 rows x 2 halves of 16 k
    int brow = tid >> 3, bnc = (tid & 7) << 3;     // 32 k-rows x 8 n-floats

    const float* Ag = A + (size_t)(m0 + arow) * K + akg;
    const float* Bg = Bm + (size_t)brow * Nsub + n0 + bnc;

    float acc[2][4][4];
#pragma unroll
    for (int i = 0; i < 2; i++)
#pragma unroll
        for (int j = 0; j < 4; j++)
#pragma unroll
            for (int e = 0; e < 4; e++) acc[i][j][e] = 0.f;

    const int nIter = K >> 5;

    // lane offsets for ldmatrix addressing (in halves)
    int aoff = (lane & 15) * ASTH + ((lane >> 4) << 3);
    int boff = (lane & 15) * BSTH + ((lane >> 4) << 3);

    float4 pa[4], pb[2];
    // prologue: load + stage iter 0
    pa[0] = *(const float4*)(Ag + 0);
    pa[1] = *(const float4*)(Ag + 4);
    pa[2] = *(const float4*)(Ag + 8);
    pa[3] = *(const float4*)(Ag + 12);
    pb[0] = *(const float4*)(Bg + 0);
    pb[1] = *(const float4*)(Bg + 4);
    {
        __half* as = Ash[0];
        uint2* dst = (uint2*)(as + arow * ASTH + akg);
        dst[0] = f4_to_h4(pa[0]); dst[1] = f4_to_h4(pa[1]);
        dst[2] = f4_to_h4(pa[2]); dst[3] = f4_to_h4(pa[3]);
        __half* bs = Bsh[0];
        uint4 bp;
        uint2 t0 = f4_to_h4(pb[0]), t1 = f4_to_h4(pb[1]);
        bp.x = t0.x; bp.y = t0.y; bp.z = t1.x; bp.w = t1.y;
        *(uint4*)(bs + brow * BSTH + bnc) = bp;
    }
    __syncthreads();

    for (int it = 0; it < nIter; it++) {
        int cur = it & 1;
        bool more = (it + 1 < nIter);
        if (more) {
            const float* a = Ag + (it + 1) * 32;
            pa[0] = *(const float4*)(a + 0);
            pa[1] = *(const float4*)(a + 4);
            pa[2] = *(const float4*)(a + 8);
            pa[3] = *(const float4*)(a + 12);
            const float* b = Bg + (size_t)(it + 1) * 32 * Nsub;
            pb[0] = *(const float4*)(b + 0);
            pb[1] = *(const float4*)(b + 4);
        }

        uint32_t a_base = smem_u32(Ash[cur]);
        uint32_t b_base = smem_u32(Bsh[cur]);
#pragma unroll
        for (int kk = 0; kk < 32; kk += 16) {
            uint32_t af[2][4], bf[2][4];
#pragma unroll
            for (int mt = 0; mt < 2; mt++) {
                uint32_t addr = a_base +
                    ((wm * 32 + mt * 16) * ASTH + kk + aoff) * 2;
                ldm_x4(af[mt][0], af[mt][1], af[mt][2], af[mt][3], addr);
            }
#pragma unroll
            for (int p = 0; p < 2; p++) {
                uint32_t addr = b_base +
                    (kk * BSTH + wn * 32 + p * 16 + boff) * 2;
                ldm_x4_t(bf[p][0], bf[p][1], bf[p][2], bf[p][3], addr);
            }
#pragma unroll
            for (int mt = 0; mt < 2; mt++) {
#pragma unroll
                for (int p = 0; p < 2; p++) {
                    mma_f16(acc[mt][p*2+0][0], acc[mt][p*2+0][1], acc[mt][p*2+0][2], acc[mt][p*2+0][3],
                            af[mt][0], af[mt][1], af[mt][2], af[mt][3],
                            bf[p][0], bf[p][1]);
                    mma_f16(acc[mt][p*2+1][0], acc[mt][p*2+1][1], acc[mt][p*2+1][2], acc[mt][p*2+1][3],
                            af[mt][0], af[mt][1], af[mt][2], af[mt][3],
                            bf[p][2], bf[p][3]);
                }
            }
        }

        if (more) {
            int nxt = cur ^ 1;
            __half* as = Ash[nxt];
            uint2* dst = (uint2*)(as + arow * ASTH + akg);
            dst[0] = f4_to_h4(pa[0]); dst[1] = f4_to_h4(pa[1]);
            dst[2] = f4_to_h4(pa[2]); dst[3] = f4_to_h4(pa[3]);
            __half* bs = Bsh[nxt];
            uint4 bp;
            uint2 t0 = f4_to_h4(pb[0]), t1 = f4_to_h4(pb[1]);
            bp.x = t0.x; bp.y = t0.y; bp.z = t1.x; bp.w = t1.y;
            *(uint4*)(bs + brow * BSTH + bnc) = bp;
            __syncthreads();
        }
    }

    // epilogue (c-frag: lane row = l>>2 (+8), col = (l&3)*2 + {0,1})
#pragma unroll
    for (int mt = 0; mt < 2; mt++) {
        int r0 = m0 + wm * 32 + mt * 16 + (lane >> 2);
#pragma unroll
        for (int nt = 0; nt < 4; nt++) {
            int c = n0 + wn * 32 + nt * 8 + ((lane & 3) << 1);
            float2 b2 = *(const float2*)(bia + c);
            float v0 = acc[mt][nt][0] + b2.x;
            float v1 = acc[mt][nt][1] + b2.y;
            float v2 = acc[mt][nt][2] + b2.x;
            float v3 = acc[mt][nt][3] + b2.y;
            if (ACT == 1) {
                v0 = gelu_tanh(v0); v1 = gelu_tanh(v1);
                v2 = gelu_tanh(v2); v3 = gelu_tanh(v3);
            }
            *(float2*)(C + (size_t)r0 * Nsub + c) = make_float2(v0, v1);
            *(float2*)(C + (size_t)(r0 + 8) * Nsub + c) = make_float2(v2, v3);
        }
    }
}

// ---------------- beta = sigmoid(x @ Wb) * mask ----------------
__global__ void beta_kernel(const float* __restrict__ Wb,
                            const int* __restrict__ amask) {
    int t = blockIdx.x;
    int w = threadIdx.x >> 5, l = threadIdx.x & 31;
    const float* xr = g_x + (size_t)t * NB_D;
    float s = 0.f;
    for (int d = l; d < NB_D; d += 32) s += xr[d] * Wb[d * NB_H + w];
    s = wsum(s);
    if (l == 0)
        g_beta[t * NB_H + w] = (float)amask[t] * (1.f / (1.f + expf(-s)));
}

// ---------------- hierarchical delta-rule scan (lane = v-column) ----------------
// One warp per (b,h). Software-pipelined: loads for step t+1 issue before the
// compute of step t, hiding gmem latency at low occupancy.
__global__ void __launch_bounds__(128)
scan_kernel(const float* __restrict__ dfast,
            const float* __restrict__ dslow,
            const float* __restrict__ mixl) {
    int bh = blockIdx.x * 4 + (threadIdx.x >> 5);
    int l = threadIdx.x & 31;
    int h = bh % NB_H;
    int b = bh / NB_H;

    float af = sigm(dfast[h]);
    float as_ = sigm(dslow[h]);
    float g = sigm(mixl[h]);
    float gi = 1.f - g;

    float Sf[32], Ss[32];
#pragma unroll
    for (int k = 0; k < 32; k++) { Sf[k] = 0.f; Ss[k] = 0.f; }

    int rb = b * NB_S * NB_D + h * NB_HD;
    int bb = b * NB_S * NB_H + h;

    float kt = g_k[rb + l];
    float qt = g_q[rb + l];
    float vt = g_v[rb + l];
    float bt = g_beta[bb];

    for (int t = 0; t < NB_S; t++) {
        float ktn = 0.f, qtn = 0.f, vtn = 0.f, btn = 0.f;
        if (t + 1 < NB_S) {
            ktn = g_k[rb + NB_D + l];
            qtn = g_q[rb + NB_D + l];
            vtn = g_v[rb + NB_D + l];
            btn = g_beta[bb + NB_H];
        }

        // fused L2 norms over the head dim
        float nk = wsum(kt * kt);
        float ktm = kt / (sqrtf(nk) + 1e-6f);
        float nq = wsum(qt * qt);
        float qtm = qt / (sqrtf(nq) + 1e-6f);

        // broadcast kt and accumulate predictions locally (per-v)
        float kk[32];
        float pf0 = 0.f, pf1 = 0.f, ps0 = 0.f, ps1 = 0.f;
#pragma unroll
        for (int k = 0; k < 32; k += 2) {
            kk[k]     = __shfl_sync(0xffffffffu, ktm, k);
            kk[k + 1] = __shfl_sync(0xffffffffu, ktm, k + 1);
            pf0 += Sf[k] * kk[k];         ps0 += Ss[k] * kk[k];
            pf1 += Sf[k + 1] * kk[k + 1]; ps1 += Ss[k + 1] * kk[k + 1];
        }
        float pf = pf0 + pf1, ps = ps0 + ps1;

        float cf = bt * (vt - pf);
        float cs = bt * (vt - ps);

        float o0 = 0.f, o1 = 0.f;
#pragma unroll
        for (int k = 0; k < 32; k += 2) {
            float qk0 = __shfl_sync(0xffffffffu, qtm, k);
            float qk1 = __shfl_sync(0xffffffffu, qtm, k + 1);
            Sf[k]     = af * Sf[k]     + kk[k] * cf;
            Ss[k]     = as_ * Ss[k]    + kk[k] * cs;
            Sf[k + 1] = af * Sf[k + 1] + kk[k + 1] * cf;
            Ss[k + 1] = as_ * Ss[k + 1] + kk[k + 1] * cs;
            o0 += qk0 * (g * Sf[k] + gi * Ss[k]);
            o1 += qk1 * (g * Sf[k + 1] + gi * Ss[k + 1]);
        }
        g_o[rb + l] = o0 + o1;

        rb += NB_D; bb += NB_H;
        kt = ktn; qt = qtn; vt = vtn; bt = btn;
    }
}

// ---------------- masked mean pool + L2 normalize ----------------
__global__ void pool_kernel(const int* __restrict__ amask,
                            float* __restrict__ out) {
    int b = blockIdx.x, d = threadIdx.x;
    float sum = 0.f, ms = 0.f;
    for (int s = 0; s < NB_S; s++) {
        float m = (float)amask[b * NB_S + s];
        sum += g_x[(size_t)(b * NB_S + s) * NB_D + d] * m;
        ms += m;
    }
    float pooled = sum / fmaxf(ms, 1e-9f);
    float sq = pooled * pooled;
    float dummy = 0.f;
    blockReduce2(sq, dummy);
    out[b * NB_D + d] = pooled * rsqrtf(sq);
}

// ---------------- launch ----------------
extern "C" void kernel_launch(void* const* d_in, const int* in_sizes, int n_in,
                              void* d_out, int out_size) {
    const int*   ids   = (const int*)d_in[0];
    const int*   amask = (const int*)d_in[1];
    const float* we    = (const float*)d_in[2];
    const float* pe    = (const float*)d_in[3];
    const float* te    = (const float*)d_in[4];
    const float* elg   = (const float*)d_in[5];
    const float* elb   = (const float*)d_in[6];
    const float* Wq    = (const float*)d_in[7];
    const float* bq    = (const float*)d_in[8];
    const float* Wk    = (const float*)d_in[9];
    const float* bk    = (const float*)d_in[10];
    const float* Wv    = (const float*)d_in[11];
    const float* bv    = (const float*)d_in[12];
    const float* Wb    = (const float*)d_in[13];
    const float* dfast = (const float*)d_in[14];
    const float* dslow = (const float*)d_in[15];
    const float* mixl  = (const float*)d_in[16];
    const float* Wo    = (const float*)d_in[17];
    const float* bo    = (const float*)d_in[18];
    const float* alg   = (const float*)d_in[19];
    const float* alb   = (const float*)d_in[20];
    const float* W1    = (const float*)d_in[21];
    const float* b1    = (const float*)d_in[22];
    const float* W2    = (const float*)d_in[23];
    const float* b2    = (const float*)d_in[24];
    const float* flg   = (const float*)d_in[25];
    const float* flb   = (const float*)d_in[26];
    float* out = (float*)d_out;

    float *p_x, *p_q, *p_k, *p_v, *p_o, *p_y, *p_h;
    cudaGetSymbolAddress((void**)&p_x, g_x);
    cudaGetSymbolAddress((void**)&p_q, g_q);
    cudaGetSymbolAddress((void**)&p_k, g_k);
    cudaGetSymbolAddress((void**)&p_v, g_v);
    cudaGetSymbolAddress((void**)&p_o, g_o);
    cudaGetSymbolAddress((void**)&p_y, g_y);
    cudaGetSymbolAddress((void**)&p_h, g_h);

    embed_ln_kernel<<<NB_T, 128>>>(ids, we, pe, te, elg, elb);

    dim3 gQKV(3 * (NB_D / 64), NB_T / 128);   // fused q,k,v
    dim3 gD(NB_D / 64, NB_T / 128);           // single N=384
    dim3 gF(NB_FF / 64, NB_T / 128);          // N=1536

    for (int l = 0; l < NB_L; l++) {
        const float* wq = Wq + (size_t)l * NB_D * NB_D;
        const float* wk = Wk + (size_t)l * NB_D * NB_D;
        const float* wv = Wv + (size_t)l * NB_D * NB_D;
        const float* wo = Wo + (size_t)l * NB_D * NB_D;
        const float* w1 = W1 + (size_t)l * NB_D * NB_FF;
        const float* w2 = W2 + (size_t)l * NB_FF * NB_D;

        // fused QKV
        h16_gemm_kernel<0><<<gQKV, 256>>>(p_x, wq, wk, wv,
                                          bq + l * NB_D, bk + l * NB_D, bv + l * NB_D,
                                          p_q, p_k, p_v,
                                          NB_T, NB_D, NB_D, NB_D / 64);

        beta_kernel<<<NB_T, NB_H * 32>>>(Wb + (size_t)l * NB_D * NB_H, amask);
        scan_kernel<<<(NB_B * NB_H) / 4, 128>>>(
            dfast + l * NB_H, dslow + l * NB_H, mixl + l * NB_H);

        h16_gemm_kernel<0><<<gD, 256>>>(p_o, wo, wo, wo,
                                        bo + l * NB_D, bo + l * NB_D, bo + l * NB_D,
                                        p_y, p_y, p_y,
                                        NB_T, NB_D, NB_D, NB_D / 64);
        add_ln_kernel<<<NB_T, 128>>>(alg + l * NB_D, alb + l * NB_D);

        h16_gemm_kernel<1><<<gF, 256>>>(p_x, w1, w1, w1,
                                        b1 + l * NB_FF, b1 + l * NB_FF, b1 + l * NB_FF,
                                        p_h, p_h, p_h,
                                        NB_T, NB_FF, NB_D, NB_FF / 64);
        h16_gemm_kernel<0><<<gD, 256>>>(p_h, w2, w2, w2,
                                        b2 + l * NB_D, b2 + l * NB_D, b2 + l * NB_D,
                                        p_y, p_y, p_y,
                                        NB_T, NB_D, NB_FF, NB_D / 64);
        add_ln_kernel<<<NB_T, 128>>>(flg + l * NB_D, flb + l * NB_D);
    }

    pool_kernel<<<NB_B, NB_D>>>(amask, out);
}